// round 5
// baseline (speedup 1.0000x reference)
#include <cuda_runtime.h>

#define W_      10
#define NSTATE  4096
#define BATCH   512
#define NIN     6
#define STAGES  2

typedef unsigned long long u64;

#define NEGB   0x8000000080000000ULL   // negate both lanes
#define MASKP  0x0000000080000000ULL   // grp4 sgn=+1: negate lo lane after swap
#define MASKM  0x8000000000000000ULL   // grp4 sgn=-1: negate hi lane after swap

// g_tab[(s*W + out)*1024 + g] = (cos(phi/2), sin(phi/2))
__device__ float2 g_tab[STAGES * W_ * 1024];
__device__ float2 u_tab[STAGES * W_];

__global__ void precompute_kernel(const float* __restrict__ unitary_theta,
                                  const float* __restrict__ neuron_theta) {
    int idx = blockIdx.x * blockDim.x + threadIdx.x;
    if (idx < STAGES * W_ * 1024) {
        int g  = idx & 1023;
        int sn = idx >> 10;
        const float* th = neuron_theta + sn * (W_ + 1);
        float phi = th[W_];
        #pragma unroll
        for (int i = 0; i < W_; i++)
            if ((g >> (9 - i)) & 1) phi += th[i];
        float sv, cv;
        sincosf(phi * 0.5f, &sv, &cv);
        g_tab[idx] = make_float2(cv, sv);
    }
    if (idx < STAGES * W_) {
        float sv, cv;
        sincosf(unitary_theta[idx] * 0.5f, &sv, &cv);
        u_tab[idx] = make_float2(cv, sv);
    }
}

// ---- packed f32x2 primitives ----
__device__ __forceinline__ u64 pk2(float lo, float hi) {
    u64 r; asm("mov.b64 %0, {%1,%2};" : "=l"(r) : "f"(lo), "f"(hi)); return r;
}
__device__ __forceinline__ u64 bcast(float v) { return pk2(v, v); }
__device__ __forceinline__ float lo32(u64 a) {
    float f; asm("{.reg .b32 x,y; mov.b64 {x,y}, %1; mov.b32 %0, x;}" : "=f"(f) : "l"(a)); return f;
}
__device__ __forceinline__ float hi32(u64 a) {
    float f; asm("{.reg .b32 x,y; mov.b64 {x,y}, %1; mov.b32 %0, y;}" : "=f"(f) : "l"(a)); return f;
}
__device__ __forceinline__ u64 f2mul(u64 a, u64 b) {
    u64 r; asm("mul.rn.f32x2 %0, %1, %2;" : "=l"(r) : "l"(a), "l"(b)); return r;
}
__device__ __forceinline__ u64 f2fma(u64 a, u64 b, u64 c) {
    u64 r; asm("fma.rn.f32x2 %0, %1, %2, %3;" : "=l"(r) : "l"(a), "l"(b), "l"(c)); return r;
}
__device__ __forceinline__ u64 lswap(u64 a) {
    u64 r; asm("{.reg .b32 x,y; mov.b64 {x,y}, %1; mov.b64 %0, {y,x};}" : "=l"(r) : "l"(a)); return r;
}
// A.hi_new = -B.hi_old ; B.hi_new = A.hi_old (lo lanes unchanged)
__device__ __forceinline__ void xswapneg(u64& a, u64& b) {
    asm("{\n\t.reg .b32 al,ah,bl,bh;\n\t"
        "mov.b64 {al,ah}, %0;\n\t"
        "mov.b64 {bl,bh}, %1;\n\t"
        "neg.f32 bh, bh;\n\t"
        "mov.b64 %0, {al,bh};\n\t"
        "mov.b64 %1, {bl,ah};\n\t}"
        : "+l"(a), "+l"(b));
}

// ---- smem swizzle (same as R4: conflict-free per phase for all sweeps)
__device__ __forceinline__ int sw4(int g) {
    return g ^ (((g >> 3) & 3) | (((g >> 2) ^ (g >> 4)) & 4));
}
__device__ __forceinline__ int swf(int i) {
    return (sw4(i >> 2) << 2) | (i & 3);
}
__device__ __forceinline__ void ld2(const float* st, int g, u64& a, u64& b) {
    ulonglong2 v = *(const ulonglong2*)(st + (sw4(g) << 2)); a = v.x; b = v.y;
}
__device__ __forceinline__ void st2(float* st, int g, u64 a, u64 b) {
    *(ulonglong2*)(st + (sw4(g) << 2)) = make_ulonglong2(a, b);
}

// ---- grp4 packed: RY(+phi) q10, CRY(sgn*pi) 10->11, RY(-phi) q10 on 4 amps
__device__ __forceinline__ void grp4p(u64& qxy, u64& qzw,
                                      u64 cc, u64 ss, u64 nss, u64 umask) {
    u64 t01 = f2fma(cc, qxy, f2mul(nss, qzw));   // (t0,t1)
    u64 t23 = f2fma(cc, qzw, f2mul(ss,  qxy));   // (t2,t3)
    u64 u23 = lswap(t23) ^ umask;                // (u2,u3)
    qxy = f2fma(cc, t01, f2mul(ss,  u23));
    qzw = f2fma(cc, u23, f2mul(nss, t01));
}

// full neuron on 8 amps (two packed groups)
__device__ __forceinline__ void neuron8p(u64& xy0, u64& zw0, u64& xy1, u64& zw1,
                                         float2 cs0, float2 cs1) {
    u64 cc0 = bcast(cs0.x), ss0 = bcast(cs0.y), nss0 = ss0 ^ NEGB;
    u64 cc1 = bcast(cs1.x), ss1 = bcast(cs1.y), nss1 = ss1 ^ NEGB;
    grp4p(xy0, zw0, cc0, ss0, nss0, MASKP);
    grp4p(xy1, zw1, cc1, ss1, nss1, MASKP);
    xswapneg(xy0, xy1);                          // CRY(pi, q11 -> target)
    xswapneg(zw0, zw1);
    grp4p(xy0, zw0, cc0, ss0, nss0, MASKM);
    grp4p(xy1, zw1, cc1, ss1, nss1, MASKM);
}

// RY pair across two packed regs: new_a = c a - s b ; new_b = s a + c b
__device__ __forceinline__ void ryp(u64& a, u64& b, u64 cc, u64 ss, u64 nss) {
    u64 na = f2fma(cc, a, f2mul(nss, b));
    u64 nb = f2fma(ss, a, f2mul(cc,  b));
    a = na; b = nb;
}
// RY within one packed reg (lane-crossing): msps = (-s, s)
__device__ __forceinline__ u64 rylane(u64 a, u64 cc, u64 msps) {
    return f2fma(cc, a, f2mul(msps, lswap(a)));
}

// apply 4 RYs to an 8xu64 register block: bits (of pair index j) 2,1,0 then lane
__device__ __forceinline__ void ry_block(u64 R[8], const float2* ut) {
    {   u64 cc = bcast(ut[0].x), ss = bcast(ut[0].y), nss = ss ^ NEGB;
        ryp(R[0], R[4], cc, ss, nss); ryp(R[1], R[5], cc, ss, nss);
        ryp(R[2], R[6], cc, ss, nss); ryp(R[3], R[7], cc, ss, nss); }
    {   u64 cc = bcast(ut[1].x), ss = bcast(ut[1].y), nss = ss ^ NEGB;
        ryp(R[0], R[2], cc, ss, nss); ryp(R[1], R[3], cc, ss, nss);
        ryp(R[4], R[6], cc, ss, nss); ryp(R[5], R[7], cc, ss, nss); }
    {   u64 cc = bcast(ut[2].x), ss = bcast(ut[2].y), nss = ss ^ NEGB;
        ryp(R[0], R[1], cc, ss, nss); ryp(R[2], R[3], cc, ss, nss);
        ryp(R[4], R[5], cc, ss, nss); ryp(R[6], R[7], cc, ss, nss); }
    {   u64 cc = bcast(ut[3].x);
        u64 msps = pk2(-ut[3].y, ut[3].y);
        #pragma unroll
        for (int j = 0; j < 8; j++) R[j] = rylane(R[j], cc, msps); }
}

// Neuron-pair sweep: neurons targeting bits PA then PA-1; item owns bits {PA,PA-1,1,0}
template <int PA>
__device__ __forceinline__ void neuron_pairp(float* st,
                                             const float2* __restrict__ tabA,
                                             const float2* __restrict__ tabB,
                                             int t) {
    constexpr int PB = PA - 1;
    constexpr int LB = PB - 2;
    const int low  = t & ((1 << LB) - 1);
    const int high = t >> LB;
    const int gb   = low | (high << (PA - 1));

    const int g00 = gb;
    const int g01 = gb + (1 << (PB - 2));
    const int g10 = gb + (1 << (PA - 2));
    const int g11 = g10 + (1 << (PB - 2));

    u64 a0, b0, a1, b1, a2, b2, a3, b3;
    ld2(st, g00, a0, b0); ld2(st, g01, a1, b1);
    ld2(st, g10, a2, b2); ld2(st, g11, a3, b3);

    neuron8p(a0, b0, a2, b2, tabA[g00], tabA[g10]);
    neuron8p(a1, b1, a3, b3, tabA[g01], tabA[g11]);
    neuron8p(a0, b0, a1, b1, tabB[g00], tabB[g01]);
    neuron8p(a2, b2, a3, b3, tabB[g10], tabB[g11]);

    st2(st, g00, a0, b0); st2(st, g01, a1, b1);
    st2(st, g10, a2, b2); st2(st, g11, a3, b3);
}

__global__ void __launch_bounds__(256, 3) sim_kernel(
    const float* __restrict__ psi_in,
    const int*   __restrict__ inp,
    float*       __restrict__ probs_out,
    float*       __restrict__ psi_out)
{
    __shared__ __align__(16) float st[NSTATE];
    __shared__ float red[256];

    const int b   = blockIdx.x;
    const int tid = threadIdx.x;

    int mask = 0;
    #pragma unroll
    for (int l = 0; l < NIN; l++) mask |= (inp[l] & 1) << (11 - l);

    #pragma unroll
    for (int s = 0; s < STAGES; s++) {
        const float2* ut = &u_tab[s * W_];

        // ---- P1: unitary lanes 0-3 (state bits 11..8). amp = tid + k*256.
        {
            u64 R[8];
            if (s == 0) {
                const float* in = psi_in + (size_t)b * NSTATE;
                #pragma unroll
                for (int j = 0; j < 8; j++)
                    R[j] = pk2(in[(tid + ((2 * j)     << 8)) ^ mask],
                               in[(tid + ((2 * j + 1) << 8)) ^ mask]);
            } else {
                #pragma unroll
                for (int j = 0; j < 8; j++)
                    R[j] = pk2(st[swf(tid + ((2 * j)     << 8))],
                               st[swf(tid + ((2 * j + 1) << 8))]);
            }
            ry_block(R, ut);      // ut[0..3] on k-bits 3,2,1,0
            #pragma unroll
            for (int j = 0; j < 8; j++) {
                st[swf(tid + ((2 * j)     << 8))] = lo32(R[j]);
                st[swf(tid + ((2 * j + 1) << 8))] = hi32(R[j]);
            }
        }
        __syncthreads();

        // ---- P2: unitary lanes 4-7 (bits 7..4). amp = base + k*16.
        {
            const int base = (tid & 15) | ((tid >> 4) << 8);
            u64 R[8];
            #pragma unroll
            for (int j = 0; j < 8; j++)
                R[j] = pk2(st[swf(base + ((2 * j)     << 4))],
                           st[swf(base + ((2 * j + 1) << 4))]);
            ry_block(R, ut + 4);  // ut[4..7]
            #pragma unroll
            for (int j = 0; j < 8; j++) {
                st[swf(base + ((2 * j)     << 4))] = lo32(R[j]);
                st[swf(base + ((2 * j + 1) << 4))] = hi32(R[j]);
            }
        }
        __syncthreads();

        // ---- P3: unitary lanes 8,9 (bits 3,2): 4 contiguous float4 groups.
        {
            u64 v[8];
            #pragma unroll
            for (int i = 0; i < 4; i++) ld2(st, (tid << 2) + i, v[2 * i], v[2 * i + 1]);
            {   u64 cc = bcast(ut[8].x), ss = bcast(ut[8].y), nss = ss ^ NEGB;  // bit 3
                ryp(v[0], v[4], cc, ss, nss); ryp(v[1], v[5], cc, ss, nss);
                ryp(v[2], v[6], cc, ss, nss); ryp(v[3], v[7], cc, ss, nss); }
            {   u64 cc = bcast(ut[9].x), ss = bcast(ut[9].y), nss = ss ^ NEGB;  // bit 2
                ryp(v[0], v[2], cc, ss, nss); ryp(v[1], v[3], cc, ss, nss);
                ryp(v[4], v[6], cc, ss, nss); ryp(v[5], v[7], cc, ss, nss); }
            #pragma unroll
            for (int i = 0; i < 4; i++) st2(st, (tid << 2) + i, v[2 * i], v[2 * i + 1]);
        }
        __syncthreads();

        // ---- P4..P7: neuron pairs (0,1),(2,3),(4,5),(6,7)
        const float2* tb = &g_tab[(s * W_) << 10];
        neuron_pairp<11>(st, tb + (0 << 10), tb + (1 << 10), tid); __syncthreads();
        neuron_pairp<9 >(st, tb + (2 << 10), tb + (3 << 10), tid); __syncthreads();
        neuron_pairp<7 >(st, tb + (4 << 10), tb + (5 << 10), tid); __syncthreads();
        neuron_pairp<5 >(st, tb + (6 << 10), tb + (7 << 10), tid); __syncthreads();

        // ---- P8: neurons 8,9 (bits 3,2). Contiguous groups g0..g0+3.
        {
            const float2* tabA = tb + (8 << 10);
            const float2* tabB = tb + (9 << 10);
            const int g0 = tid << 2;
            u64 a0, b0, a1, b1, a2, b2, a3, b3;
            ld2(st, g0,     a0, b0); ld2(st, g0 + 1, a1, b1);
            ld2(st, g0 + 2, a2, b2); ld2(st, g0 + 3, a3, b3);

            neuron8p(a0, b0, a2, b2, tabA[g0],     tabA[g0 + 2]);
            neuron8p(a1, b1, a3, b3, tabA[g0 + 1], tabA[g0 + 3]);
            neuron8p(a0, b0, a1, b1, tabB[g0],     tabB[g0 + 1]);
            neuron8p(a2, b2, a3, b3, tabB[g0 + 2], tabB[g0 + 3]);

            if (s == STAGES - 1) {
                ulonglong2* out2 = (ulonglong2*)(psi_out + (size_t)b * NSTATE);
                out2[g0]     = make_ulonglong2(a0, b0);
                out2[g0 + 1] = make_ulonglong2(a1, b1);
                out2[g0 + 2] = make_ulonglong2(a2, b2);
                out2[g0 + 3] = make_ulonglong2(a3, b3);
                float ssq = 0.f;
                u64 q[8] = {a0, b0, a1, b1, a2, b2, a3, b3};
                #pragma unroll
                for (int j = 0; j < 8; j++) {
                    float l = lo32(q[j]), h = hi32(q[j]);
                    ssq += l * l + h * h;
                }
                red[tid] = ssq;
            } else {
                st2(st, g0,     a0, b0); st2(st, g0 + 1, a1, b1);
                st2(st, g0 + 2, a2, b2); st2(st, g0 + 3, a3, b3);
            }
        }
        __syncthreads();
    }

    if (tid < 64) {
        probs_out[b * 64 + tid] =
            red[4 * tid] + red[4 * tid + 1] + red[4 * tid + 2] + red[4 * tid + 3];
    }
}

extern "C" void kernel_launch(void* const* d_in, const int* in_sizes, int n_in,
                              void* d_out, int out_size) {
    const float* psi = (const float*)d_in[0];
    const int*   inp = (const int*)d_in[1];
    const float* uth = (const float*)d_in[2];
    const float* nth = (const float*)d_in[3];
    float* out = (float*)d_out;

    float* probs_out = out;
    float* psi_out   = out + BATCH * 64;

    precompute_kernel<<<(STAGES * W_ * 1024 + 255) / 256, 256>>>(uth, nth);
    sim_kernel<<<BATCH, 256>>>(psi, inp, probs_out, psi_out);
}